// round 16
// baseline (speedup 1.0000x reference)
#include <cuda_runtime.h>
#include <math.h>
#include <stdint.h>

#define BB 2
#define NN 2048
#define CC 1024
#define HH 16
#define DD 64
#define C3 (3*CC)
#define MM (BB*NN)   /* 4096 rows */

// Scratch (device globals: allocation-free per harness rules)
__device__ float g_q[(size_t)BB*HH*NN*DD];
__device__ float g_k[(size_t)BB*HH*NN*DD];
__device__ float g_v[(size_t)BB*HH*NN*DD];
__device__ float g_ret[(size_t)MM*CC];
__device__ float g_spart[(size_t)BB*HH*32*DD*DD];   // state partials [bh][chunk][d][e]

__device__ __forceinline__ uint32_t f2tf(float f) {
    uint32_t u; asm("cvt.rna.tf32.f32 %0, %1;" : "=r"(u) : "f"(f)); return u;
}

__device__ __forceinline__ void mma_tf32(float* d,
                                         const uint32_t* a,
                                         const uint32_t* b,
                                         const float* c) {
    asm volatile(
        "mma.sync.aligned.m16n8k8.row.col.f32.tf32.tf32.f32 "
        "{%0,%1,%2,%3}, {%4,%5,%6,%7}, {%8,%9}, {%10,%11,%12,%13};"
        : "=f"(d[0]), "=f"(d[1]), "=f"(d[2]), "=f"(d[3])
        : "r"(a[0]), "r"(a[1]), "r"(a[2]), "r"(a[3]),
          "r"(b[0]), "r"(b[1]),
          "f"(c[0]), "f"(c[1]), "f"(c[2]), "f"(c[3]));
}

// shared epilogue for both GEMM variants
template<int MODE>
__device__ __forceinline__ void gemm_epilogue(
        float acc[2][8][4], const float* __restrict__ bias,
        float* __restrict__ out, int bm, int bn,
        int warpM, int warpN, int lr, int lc) {
    if (MODE == 0) {
        const int which = bn >> 10;
        float* dst = (which == 0) ? g_q : (which == 1) ? g_k : g_v;
        const float qscale = (which == 0) ? 0.125f : 1.0f;
        #pragma unroll
        for (int mt = 0; mt < 2; mt++) {
            #pragma unroll
            for (int nt = 0; nt < 8; nt++) {
                const int col = bn + warpN*64 + nt*8 + 2*lc;
                const int h   = (col >> 6) & (HH-1);
                const int dd  = col & 63;
                const float b0 = bias[col], b1 = bias[col+1];
                #pragma unroll
                for (int rh = 0; rh < 2; rh++) {
                    const int m = bm + warpM*32 + mt*16 + lr + rh*8;
                    const int b = m >> 11;
                    const int n = m & (NN-1);
                    float2 o;
                    o.x = (acc[mt][nt][rh*2+0] + b0) * qscale;
                    o.y = (acc[mt][nt][rh*2+1] + b1) * qscale;
                    *(float2*)(dst + (((size_t)b*HH + h)*NN + n)*DD + dd) = o;
                }
            }
        }
    } else {
        #pragma unroll
        for (int mt = 0; mt < 2; mt++) {
            #pragma unroll
            for (int nt = 0; nt < 8; nt++) {
                const int col = bn + warpN*64 + nt*8 + 2*lc;
                const float b0 = bias[col], b1 = bias[col+1];
                #pragma unroll
                for (int rh = 0; rh < 2; rh++) {
                    const int m = bm + warpM*32 + mt*16 + lr + rh*8;
                    float2 o;
                    o.x = acc[mt][nt][rh*2+0] + b0;
                    o.y = acc[mt][nt][rh*2+1] + b1;
                    *(float2*)(out + (size_t)m*CC + col) = o;
                }
            }
        }
    }
}

// ---------------------------------------------------------------------------
// GEMM variant A: BK=32 double-buffered, DYNAMIC smem 68,608 B (needs attr).
// Conflict-free As stores: arow=((tid>>1)&15)+16*(tid>>5), akq=4*(tid&1)+8p
//   -> store bank = 16*(tid&1) + 4j + r  (bijective over warp).
// Bs stores STS.128 conflict-free per quarter-warp. Fragment reads unchanged
// (As pitch 132, Bs pitch 136 — both bank-bijective).
// ---------------------------------------------------------------------------
template<int MODE>
__global__ void __launch_bounds__(256) gemm32_kernel(
        const float* __restrict__ A,
        const float* __restrict__ Bm,
        const float* __restrict__ bias,
        float* __restrict__ out,
        int lda, int ldb) {
    extern __shared__ uint32_t dyn[];
    uint32_t* Asm = dyn;               // [2][32*132]
    uint32_t* Bsm = dyn + 2*32*132;    // [2][32*136]
    const float* __restrict__ Ap = (MODE == 1) ? (const float*)g_ret : A;
    const int bm = blockIdx.y * 128;
    const int bn = blockIdx.x * 128;
    const int tid  = threadIdx.x;
    const int lane = tid & 31;
    const int wid  = tid >> 5;
    const int warpM = wid >> 1;
    const int warpN = wid & 1;
    const int lr = lane >> 2;
    const int lc = lane & 3;

    const int arow = ((tid >> 1) & 15) | ((tid >> 5) << 4);  // 0..127
    const int akq0 = (tid & 1) * 4;
    const int bkr0 = tid >> 5;          // +8p
    const int bnq  = (tid & 31) * 4;

    float4 aR[4], bR[4];

#define G32_LOAD(k0) do { \
        _Pragma("unroll") \
        for (int p = 0; p < 4; p++) { \
            aR[p] = *(const float4*)(Ap + (size_t)(bm + arow)*lda + (k0) + akq0 + 8*p); \
            bR[p] = *(const float4*)(Bm + (size_t)((k0) + bkr0 + 8*p)*ldb + bn + bnq); \
        } \
    } while (0)

#define G32_STORE(buf) do { \
        uint32_t* Ab = Asm + (buf)*(32*132); \
        uint32_t* Bb = Bsm + (buf)*(32*136); \
        _Pragma("unroll") \
        for (int p = 0; p < 4; p++) { \
            const int kq = akq0 + 8*p; \
            Ab[(kq+0)*132 + arow] = f2tf(aR[p].x); \
            Ab[(kq+1)*132 + arow] = f2tf(aR[p].y); \
            Ab[(kq+2)*132 + arow] = f2tf(aR[p].z); \
            Ab[(kq+3)*132 + arow] = f2tf(aR[p].w); \
            *(uint4*)&Bb[(bkr0 + 8*p)*136 + bnq] = \
                make_uint4(f2tf(bR[p].x), f2tf(bR[p].y), f2tf(bR[p].z), f2tf(bR[p].w)); \
        } \
    } while (0)

    G32_LOAD(0);
    G32_STORE(0);
    __syncthreads();

    float acc[2][8][4] = {};

    for (int kt = 0; kt < 32; kt++) {
        const int buf = kt & 1;
        if (kt + 1 < 32) G32_LOAD((kt + 1) * 32);

        const uint32_t* Ab = Asm + buf*(32*132);
        const uint32_t* Bb = Bsm + buf*(32*136);
        #pragma unroll
        for (int ks = 0; ks < 4; ks++) {
            uint32_t afr[2][4], bfr[8][2];
            const int col = ks*8 + lc;
            #pragma unroll
            for (int mt = 0; mt < 2; mt++) {
                const int row = warpM*32 + mt*16 + lr;
                afr[mt][0] = Ab[(col  )*132 + row    ];
                afr[mt][1] = Ab[(col  )*132 + row + 8];
                afr[mt][2] = Ab[(col+4)*132 + row    ];
                afr[mt][3] = Ab[(col+4)*132 + row + 8];
            }
            #pragma unroll
            for (int nt = 0; nt < 8; nt++) {
                const int n = warpN*64 + nt*8 + lr;
                bfr[nt][0] = Bb[(col    )*136 + n];
                bfr[nt][1] = Bb[(col + 4)*136 + n];
            }
            #pragma unroll
            for (int mt = 0; mt < 2; mt++)
                #pragma unroll
                for (int nt = 0; nt < 8; nt++)
                    mma_tf32(acc[mt][nt], afr[mt], bfr[nt], acc[mt][nt]);
        }

        if (kt + 1 < 32) G32_STORE(buf ^ 1);
        __syncthreads();
    }
#undef G32_LOAD
#undef G32_STORE

    gemm_epilogue<MODE>(acc, bias, out, bm, bn, warpM, warpN, lr, lc);
}

// ---------------------------------------------------------------------------
// GEMM variant B (fallback): BK=16 double-buffered, static smem (R12 exact).
// ---------------------------------------------------------------------------
template<int MODE>
__global__ void __launch_bounds__(256) gemm16_kernel(
        const float* __restrict__ A,
        const float* __restrict__ Bm,
        const float* __restrict__ bias,
        float* __restrict__ out,
        int lda, int ldb) {
    __shared__ uint32_t As[2][16*132];
    __shared__ uint32_t Bs[2][16*136];
    const float* __restrict__ Ap = (MODE == 1) ? (const float*)g_ret : A;
    const int bm = blockIdx.y * 128;
    const int bn = blockIdx.x * 128;
    const int tid  = threadIdx.x;
    const int lane = tid & 31;
    const int wid  = tid >> 5;
    const int warpM = wid >> 1;
    const int warpN = wid & 1;
    const int lr = lane >> 2;
    const int lc = lane & 3;

    const int arow = tid >> 2;
    const int akq  = (tid & 3) * 4;
    const int bkr  = tid >> 5;
    const int bnq  = (tid & 31) * 4;

    float4 aR0, aR1, bR0, bR1;

#define G16_LOAD(k0) do { \
        aR0 = *(const float4*)(Ap + (size_t)(bm + arow     )*lda + (k0) + akq); \
        aR1 = *(const float4*)(Ap + (size_t)(bm + arow + 64)*lda + (k0) + akq); \
        bR0 = *(const float4*)(Bm + (size_t)((k0) + bkr    )*ldb + bn + bnq); \
        bR1 = *(const float4*)(Bm + (size_t)((k0) + bkr + 8)*ldb + bn + bnq); \
    } while (0)

#define G16_STORE(buf) do { \
        As[buf][(akq+0)*132 + arow     ] = f2tf(aR0.x); \
        As[buf][(akq+1)*132 + arow     ] = f2tf(aR0.y); \
        As[buf][(akq+2)*132 + arow     ] = f2tf(aR0.z); \
        As[buf][(akq+3)*132 + arow     ] = f2tf(aR0.w); \
        As[buf][(akq+0)*132 + arow + 64] = f2tf(aR1.x); \
        As[buf][(akq+1)*132 + arow + 64] = f2tf(aR1.y); \
        As[buf][(akq+2)*132 + arow + 64] = f2tf(aR1.z); \
        As[buf][(akq+3)*132 + arow + 64] = f2tf(aR1.w); \
        *(uint4*)&Bs[buf][(bkr    )*136 + bnq] = \
            make_uint4(f2tf(bR0.x), f2tf(bR0.y), f2tf(bR0.z), f2tf(bR0.w)); \
        *(uint4*)&Bs[buf][(bkr + 8)*136 + bnq] = \
            make_uint4(f2tf(bR1.x), f2tf(bR1.y), f2tf(bR1.z), f2tf(bR1.w)); \
    } while (0)

    G16_LOAD(0);
    G16_STORE(0);
    __syncthreads();

    float acc[2][8][4] = {};

    for (int kt = 0; kt < 64; kt++) {
        const int buf = kt & 1;
        if (kt + 1 < 64) G16_LOAD((kt + 1) * 16);

        #pragma unroll
        for (int ks = 0; ks < 2; ks++) {
            uint32_t afr[2][4], bfr[8][2];
            const int col = ks*8 + lc;
            #pragma unroll
            for (int mt = 0; mt < 2; mt++) {
                const int row = warpM*32 + mt*16 + lr;
                afr[mt][0] = As[buf][(col  )*132 + row    ];
                afr[mt][1] = As[buf][(col  )*132 + row + 8];
                afr[mt][2] = As[buf][(col+4)*132 + row    ];
                afr[mt][3] = As[buf][(col+4)*132 + row + 8];
            }
            #pragma unroll
            for (int nt = 0; nt < 8; nt++) {
                const int n = warpN*64 + nt*8 + lr;
                bfr[nt][0] = Bs[buf][(col    )*136 + n];
                bfr[nt][1] = Bs[buf][(col + 4)*136 + n];
            }
            #pragma unroll
            for (int mt = 0; mt < 2; mt++)
                #pragma unroll
                for (int nt = 0; nt < 8; nt++)
                    mma_tf32(acc[mt][nt], afr[mt], bfr[nt], acc[mt][nt]);
        }

        if (kt + 1 < 64) G16_STORE(buf ^ 1);
        __syncthreads();
    }
#undef G16_LOAD
#undef G16_STORE

    gemm_epilogue<MODE>(acc, bias, out, bm, bn, warpM, warpN, lr, lc);
}

// ---------------------------------------------------------------------------
// Fused retention (tf32 mma) — R15 version (best measured). k stored natural
// [m][d] pitch 68 (conflict-free stores + reads); vsh [m][e] pitch 72.
// ---------------------------------------------------------------------------
__global__ void __launch_bounds__(256) retention_tf32_kernel(
        const float* __restrict__ mask,
        const float* __restrict__ gamma,
        const float* __restrict__ state_prev) {
    __shared__ uint32_t ksh[64*68];  // [m][d] natural
    __shared__ uint32_t vsh[64*72];  // [m][e] natural; reused: sp [d][e] pitch 72

    const int bh = blockIdx.y;
    const int b = bh & 1, h = bh >> 1;         // mask-L2 pairing
    const int bhq = b*HH + h;
    const int n0 = blockIdx.x * 128;
    const int tid  = threadIdx.x;
    const int lane = tid & 31;
    const int wid  = tid >> 5;
    const int lr = lane >> 2, lc = lane & 3;

    const float* qbase = g_q + (size_t)bhq*NN*DD;
    const float* kbase = g_k + (size_t)bhq*NN*DD;
    const float* vbase = g_v + (size_t)bhq*NN*DD;
    const float* mbase = mask + (size_t)h*NN*NN;

    const int rowg = n0 + wid*16 + lr;

    uint32_t qfr[8][4];
    {
        const float* q0 = qbase + (size_t)rowg*DD;
        const float* q8 = qbase + (size_t)(rowg + 8)*DD;
        #pragma unroll
        for (int ks = 0; ks < 8; ks++) {
            const int col = ks*8 + lc;
            qfr[ks][0] = f2tf(q0[col    ]);
            qfr[ks][1] = f2tf(q8[col    ]);
            qfr[ks][2] = f2tf(q0[col + 4]);
            qfr[ks][3] = f2tf(q8[col + 4]);
        }
    }

    const int idxA = lr*4 + (lc >> 1);
    const int idxB = idxA + 2;
    const bool sel = (lc & 1);

    float o[8][4] = {};

    for (int mt = 0; mt < 32; mt++) {
        const int m0 = mt*64;
        __syncthreads();
        #pragma unroll
        for (int i = 0; i < 4; i++) {
            const int fidx = i*256 + tid;
            const int m = fidx >> 4;
            const int dq = (fidx & 15) * 4;
            const float4 kv = *(const float4*)(kbase + (size_t)(m0 + m)*DD + dq);
            *(uint4*)&ksh[m*68 + dq] =
                make_uint4(f2tf(kv.x), f2tf(kv.y), f2tf(kv.z), f2tf(kv.w));
            const float4 vv = *(const float4*)(vbase + (size_t)(m0 + m)*DD + dq);
            *(uint4*)&vsh[m*72 + dq] =
                make_uint4(f2tf(vv.x), f2tf(vv.y), f2tf(vv.z), f2tf(vv.w));
        }
        __syncthreads();

        float s[8][4] = {};
        #pragma unroll
        for (int ks = 0; ks < 8; ks++) {
            const int col = ks*8 + lc;
            uint32_t bfr[8][2];
            #pragma unroll
            for (int nt = 0; nt < 8; nt++) {
                const int n = nt*8 + lr;
                bfr[nt][0] = ksh[n*68 + col    ];
                bfr[nt][1] = ksh[n*68 + col + 4];
            }
            #pragma unroll
            for (int nt = 0; nt < 8; nt++)
                mma_tf32(s[nt], qfr[ks], bfr[nt], s[nt]);
        }
        #pragma unroll
        for (int nt = 0; nt < 8; nt++) {
            const int colg = m0 + nt*8 + 2*lc;
            const float2 m01 = *(const float2*)(mbase + (size_t)rowg*NN + colg);
            const float2 m23 = *(const float2*)(mbase + (size_t)(rowg+8)*NN + colg);
            s[nt][0] *= m01.x; s[nt][1] *= m01.y;
            s[nt][2] *= m23.x; s[nt][3] *= m23.y;
        }
        #pragma unroll
        for (int ks = 0; ks < 8; ks++) {
            const float t0A = __shfl_sync(0xffffffffu, s[ks][0], idxA);
            const float t1A = __shfl_sync(0xffffffffu, s[ks][1], idxA);
            const float t2A = __shfl_sync(0xffffffffu, s[ks][2], idxA);
            const float t3A = __shfl_sync(0xffffffffu, s[ks][3], idxA);
            const float t0B = __shfl_sync(0xffffffffu, s[ks][0], idxB);
            const float t1B = __shfl_sync(0xffffffffu, s[ks][1], idxB);
            const float t2B = __shfl_sync(0xffffffffu, s[ks][2], idxB);
            const float t3B = __shfl_sync(0xffffffffu, s[ks][3], idxB);
            uint32_t a[4];
            a[0] = f2tf(sel ? t1A : t0A);
            a[1] = f2tf(sel ? t3A : t2A);
            a[2] = f2tf(sel ? t1B : t0B);
            a[3] = f2tf(sel ? t3B : t2B);
            const int col = ks*8 + lc;
            uint32_t bfr[8][2];
            #pragma unroll
            for (int nt = 0; nt < 8; nt++) {
                const int n = nt*8 + lr;
                bfr[nt][0] = vsh[(col    )*72 + n];
                bfr[nt][1] = vsh[(col + 4)*72 + n];
            }
            #pragma unroll
            for (int nt = 0; nt < 8; nt++)
                mma_tf32(o[nt], a, bfr[nt], o[nt]);
        }
    }

    __syncthreads();
    uint32_t* sps = vsh;   // [d][e] pitch 72
    #pragma unroll
    for (int i = 0; i < 4; i++) {
        const int fidx = i*256 + tid;
        const int d = fidx >> 4;
        const int eq = (fidx & 15) * 4;
        const float4 v = *(const float4*)(state_prev + ((size_t)bhq*DD + d)*DD + eq);
        *(uint4*)&sps[d*72 + eq] =
            make_uint4(f2tf(v.x), f2tf(v.y), f2tf(v.z), f2tf(v.w));
    }
    __syncthreads();
    float cr[8][4] = {};
    #pragma unroll
    for (int ks = 0; ks < 8; ks++) {
        const int col = ks*8 + lc;
        uint32_t bfr[8][2];
        #pragma unroll
        for (int nt = 0; nt < 8; nt++) {
            const int n = nt*8 + lr;
            bfr[nt][0] = sps[(col    )*72 + n];
            bfr[nt][1] = sps[(col + 4)*72 + n];
        }
        #pragma unroll
        for (int nt = 0; nt < 8; nt++)
            mma_tf32(cr[nt], qfr[ks], bfr[nt], cr[nt]);
    }
    const float lg = logf(gamma[h]);
    const float sc0 = expf(lg * (float)(rowg + 1));
    const float sc1 = expf(lg * (float)(rowg + 9));
    #pragma unroll
    for (int nt = 0; nt < 8; nt++) {
        o[nt][0] += cr[nt][0]*sc0; o[nt][1] += cr[nt][1]*sc0;
        o[nt][2] += cr[nt][2]*sc1; o[nt][3] += cr[nt][3]*sc1;
    }
    #pragma unroll
    for (int nt = 0; nt < 8; nt++) {
        const int e = nt*8 + 2*lc;
        *(float2*)(g_ret + ((size_t)b*NN + rowg    )*CC + h*64 + e) = make_float2(o[nt][0], o[nt][1]);
        *(float2*)(g_ret + ((size_t)b*NN + rowg + 8)*CC + h*64 + e) = make_float2(o[nt][2], o[nt][3]);
    }
}

// ---------------------------------------------------------------------------
// Kernel 3a: per-chunk partial state (unchanged).
// ---------------------------------------------------------------------------
__global__ void state_partial_kernel(const float* __restrict__ gamma) {
    __shared__ float ksh[64*65];
    __shared__ float vsh[64*65];
    const int chunk = blockIdx.x;
    const int bh    = blockIdx.y;
    const int h = bh & 15;
    const int tid = threadIdx.x;
    const int tx = tid & 15, ty = tid >> 4;
    const int n0 = chunk * 64;
    const float* kbase = g_k + (size_t)bh*NN*DD;
    const float* vbase = g_v + (size_t)bh*NN*DD;
    const float lg = logf(gamma[h]);
    #pragma unroll
    for (int p = 0; p < 16; p++) {
        const int idx = p*256 + tid;
        const int r = idx >> 6, d = idx & 63;
        const int n = n0 + r;
        const float decay = expf(lg * (float)(NN - 1 - n));
        ksh[r*65 + d] = kbase[(size_t)n*DD + d] * decay;
        vsh[r*65 + d] = vbase[(size_t)n*DD + d];
    }
    __syncthreads();
    float acc[4][4] = {};
    #pragma unroll
    for (int r = 0; r < 64; r++) {
        float kk[4], vv[4];
        #pragma unroll
        for (int i = 0; i < 4; i++) kk[i] = ksh[r*65 + ty*4 + i];
        #pragma unroll
        for (int j = 0; j < 4; j++) vv[j] = vsh[r*65 + tx*4 + j];
        #pragma unroll
        for (int i = 0; i < 4; i++)
            #pragma unroll
            for (int j = 0; j < 4; j++)
                acc[i][j] += kk[i]*vv[j];
    }
    float* dst = g_spart + ((size_t)bh*32 + chunk)*DD*DD;
    #pragma unroll
    for (int i = 0; i < 4; i++)
        #pragma unroll
        for (int j = 0; j < 4; j++)
            dst[(ty*4 + i)*DD + tx*4 + j] = acc[i][j];
}

// ---------------------------------------------------------------------------
// Kernel 3b: reduce partials + state_prev*gamma^N -> out_state (unchanged).
// ---------------------------------------------------------------------------
__global__ void state_reduce_kernel(const float* __restrict__ gamma,
                                    const float* __restrict__ state_prev,
                                    float* __restrict__ out_state) {
    const int bh = blockIdx.x;
    const int h = bh & 15;
    const int e = blockIdx.y*256 + threadIdx.x;
    const float cd = expf(logf(gamma[h]) * (float)NN);
    const float* part = g_spart + (size_t)bh*32*DD*DD;
    float sum = 0.0f;
    #pragma unroll
    for (int c = 0; c < 32; c++) sum += part[(size_t)c*DD*DD + e];
    out_state[(size_t)bh*DD*DD + e] = sum + state_prev[(size_t)bh*DD*DD + e]*cd;
}

// ---------------------------------------------------------------------------
extern "C" void kernel_launch(void* const* d_in, const int* in_sizes, int n_in,
                              void* d_out, int out_size) {
    const float* x          = (const float*)d_in[0];
    const float* mask       = (const float*)d_in[1];
    const float* gamma      = (const float*)d_in[2];
    const float* state_prev = (const float*)d_in[3];
    const float* W_qkv      = (const float*)d_in[4];
    const float* b_qkv      = (const float*)d_in[5];
    const float* W_out      = (const float*)d_in[6];
    const float* b_out      = (const float*)d_in[7];
    float* out = (float*)d_out;
    float* out_state = out + (size_t)MM*CC;

    // Opt-in to 68,608 B dynamic smem for the BK=32 GEMMs. Unguarded
    // (idempotent, deterministic). Fallback to BK=16 static if it fails.
    const int G32_SMEM = (2*32*132 + 2*32*136) * 4;
    bool ok32 =
        (cudaFuncSetAttribute(gemm32_kernel<0>,
            cudaFuncAttributeMaxDynamicSharedMemorySize, G32_SMEM) == cudaSuccess) &&
        (cudaFuncSetAttribute(gemm32_kernel<1>,
            cudaFuncAttributeMaxDynamicSharedMemorySize, G32_SMEM) == cudaSuccess);

    if (ok32)
        gemm32_kernel<0><<<dim3(C3/128, MM/128), 256, G32_SMEM>>>(x, W_qkv, b_qkv, nullptr, CC, C3);
    else
        gemm16_kernel<0><<<dim3(C3/128, MM/128), 256>>>(x, W_qkv, b_qkv, nullptr, CC, C3);

    retention_tf32_kernel<<<dim3(NN/128, BB*HH), 256>>>(mask, gamma, state_prev);
    state_partial_kernel<<<dim3(32, BB*HH), 256>>>(gamma);
    state_reduce_kernel<<<dim3(BB*HH, 16), 256>>>(gamma, state_prev, out_state);

    // MODE 1 resolves its A pointer (g_ret) in device code; first arg unused.
    if (ok32)
        gemm32_kernel<1><<<dim3(CC/128, MM/128), 256, G32_SMEM>>>(nullptr, W_out, b_out, out, CC, CC);
    else
        gemm16_kernel<1><<<dim3(CC/128, MM/128), 256>>>(nullptr, W_out, b_out, out, CC, CC);
}

// round 17
// speedup vs baseline: 1.1703x; 1.1703x over previous
#include <cuda_runtime.h>
#include <math.h>
#include <stdint.h>

#define BB 2
#define NN 2048
#define CC 1024
#define HH 16
#define DD 64
#define C3 (3*CC)
#define MM (BB*NN)   /* 4096 rows */

// Scratch (device globals: allocation-free per harness rules)
__device__ float g_q[(size_t)BB*HH*NN*DD];
__device__ float g_k[(size_t)BB*HH*NN*DD];
__device__ float g_v[(size_t)BB*HH*NN*DD];
__device__ float g_ret[(size_t)MM*CC];
__device__ float g_spart[(size_t)BB*HH*32*DD*DD];   // state partials [bh][chunk][d][e]

__device__ __forceinline__ uint32_t f2tf(float f) {
    uint32_t u; asm("cvt.rna.tf32.f32 %0, %1;" : "=r"(u) : "f"(f)); return u;
}

__device__ __forceinline__ void mma_tf32(float* d,
                                         const uint32_t* a,
                                         const uint32_t* b,
                                         const float* c) {
    asm volatile(
        "mma.sync.aligned.m16n8k8.row.col.f32.tf32.tf32.f32 "
        "{%0,%1,%2,%3}, {%4,%5,%6,%7}, {%8,%9}, {%10,%11,%12,%13};"
        : "=f"(d[0]), "=f"(d[1]), "=f"(d[2]), "=f"(d[3])
        : "r"(a[0]), "r"(a[1]), "r"(a[2]), "r"(a[3]),
          "r"(b[0]), "r"(b[1]),
          "f"(c[0]), "f"(c[1]), "f"(c[2]), "f"(c[3]));
}

// ---------------------------------------------------------------------------
// tf32 GEMM, double-buffered BK=16 (R12 structure) with fully conflict-free
// smem: As pitch 136 + XOR row swizzle  row' = row ^ 8*((kq>>2)&3)
//   - A stores: bank = 8(j+a)+b  (bijective over warp)
//   - A-frag reads: bank = 8lc+lr+const (bijective)
//   - Bs pitch 136: STS.128 stores + reads conflict-free (as before)
// Same values, same accumulation order -> bit-identical output.
// MODE 0: qkv split epilogue. MODE 1: A = g_ret (device symbol), out + bias.
// ---------------------------------------------------------------------------
template<int MODE>
__global__ void __launch_bounds__(256) gemm_tf32_kernel(
        const float* __restrict__ A,
        const float* __restrict__ Bm,
        const float* __restrict__ bias,
        float* __restrict__ out,
        int lda, int ldb) {
    __shared__ uint32_t As[2][16*136];  // [k][m^swz] pitch 136
    __shared__ uint32_t Bs[2][16*136];  // [k][n] pitch 136
    const float* __restrict__ Ap = (MODE == 1) ? (const float*)g_ret : A;
    const int bm = blockIdx.y * 128;
    const int bn = blockIdx.x * 128;
    const int tid  = threadIdx.x;
    const int lane = tid & 31;
    const int wid  = tid >> 5;
    const int warpM = wid >> 1;
    const int warpN = wid & 1;
    const int lr = lane >> 2;
    const int lc = lane & 3;

    const int arow = tid >> 2;          // rows arow, arow+64
    const int akq  = (tid & 3) * 4;
    const int axr  = 8 * (tid & 3);     // store row-XOR = 8*((kq>>2)&3), kq=akq+j
    const int bkr  = tid >> 5;          // k-rows bkr, bkr+8
    const int bnq  = (tid & 31) * 4;

    const int arow0 = arow ^ axr;       // swizzled row for rows 0..63
    const int arow1 = (arow + 64) ^ axr;

    float4 aR0, aR1, bR0, bR1;

#define LOAD_TILE(k0) do { \
        aR0 = *(const float4*)(Ap + (size_t)(bm + arow     )*lda + (k0) + akq); \
        aR1 = *(const float4*)(Ap + (size_t)(bm + arow + 64)*lda + (k0) + akq); \
        bR0 = *(const float4*)(Bm + (size_t)((k0) + bkr    )*ldb + bn + bnq); \
        bR1 = *(const float4*)(Bm + (size_t)((k0) + bkr + 8)*ldb + bn + bnq); \
    } while (0)

#define STORE_TILE(buf) do { \
        As[buf][(akq+0)*136 + arow0] = f2tf(aR0.x); \
        As[buf][(akq+1)*136 + arow0] = f2tf(aR0.y); \
        As[buf][(akq+2)*136 + arow0] = f2tf(aR0.z); \
        As[buf][(akq+3)*136 + arow0] = f2tf(aR0.w); \
        As[buf][(akq+0)*136 + arow1] = f2tf(aR1.x); \
        As[buf][(akq+1)*136 + arow1] = f2tf(aR1.y); \
        As[buf][(akq+2)*136 + arow1] = f2tf(aR1.z); \
        As[buf][(akq+3)*136 + arow1] = f2tf(aR1.w); \
        *(uint4*)&Bs[buf][(bkr    )*136 + bnq] = \
            make_uint4(f2tf(bR0.x), f2tf(bR0.y), f2tf(bR0.z), f2tf(bR0.w)); \
        *(uint4*)&Bs[buf][(bkr + 8)*136 + bnq] = \
            make_uint4(f2tf(bR1.x), f2tf(bR1.y), f2tf(bR1.z), f2tf(bR1.w)); \
    } while (0)

    LOAD_TILE(0);
    STORE_TILE(0);
    __syncthreads();

    float acc[2][8][4] = {};

    for (int kt = 0; kt < 64; kt++) {
        const int buf = kt & 1;
        if (kt + 1 < 64) LOAD_TILE((kt + 1) * 16);

        #pragma unroll
        for (int ks = 0; ks < 2; ks++) {
            uint32_t afr[2][4], bfr[8][2];
            const int col = ks*8 + lc;
            const int x1 = 8 * ((2*ks    ) & 3);   // f(col)
            const int x2 = 8 * ((2*ks + 1) & 3);   // f(col+4)
            #pragma unroll
            for (int mt = 0; mt < 2; mt++) {
                const int row = warpM*32 + mt*16 + lr;
                afr[mt][0] = As[buf][(col  )*136 + (row       ^ x1)];
                afr[mt][1] = As[buf][(col  )*136 + ((row + 8) ^ x1)];
                afr[mt][2] = As[buf][(col+4)*136 + (row       ^ x2)];
                afr[mt][3] = As[buf][(col+4)*136 + ((row + 8) ^ x2)];
            }
            #pragma unroll
            for (int nt = 0; nt < 8; nt++) {
                const int n = warpN*64 + nt*8 + lr;
                bfr[nt][0] = Bs[buf][(col    )*136 + n];
                bfr[nt][1] = Bs[buf][(col + 4)*136 + n];
            }
            #pragma unroll
            for (int mt = 0; mt < 2; mt++)
                #pragma unroll
                for (int nt = 0; nt < 8; nt++)
                    mma_tf32(acc[mt][nt], afr[mt], bfr[nt], acc[mt][nt]);
        }

        if (kt + 1 < 64) STORE_TILE(buf ^ 1);
        __syncthreads();
    }

#undef LOAD_TILE
#undef STORE_TILE

    if (MODE == 0) {
        const int which = bn >> 10;
        float* dst = (which == 0) ? g_q : (which == 1) ? g_k : g_v;
        const float qscale = (which == 0) ? 0.125f : 1.0f;
        #pragma unroll
        for (int mt = 0; mt < 2; mt++) {
            #pragma unroll
            for (int nt = 0; nt < 8; nt++) {
                const int col = bn + warpN*64 + nt*8 + 2*lc;
                const int h   = (col >> 6) & (HH-1);
                const int dd  = col & 63;
                const float b0 = bias[col], b1 = bias[col+1];
                #pragma unroll
                for (int rh = 0; rh < 2; rh++) {
                    const int m = bm + warpM*32 + mt*16 + lr + rh*8;
                    const int b = m >> 11;
                    const int n = m & (NN-1);
                    float2 o;
                    o.x = (acc[mt][nt][rh*2+0] + b0) * qscale;
                    o.y = (acc[mt][nt][rh*2+1] + b1) * qscale;
                    *(float2*)(dst + (((size_t)b*HH + h)*NN + n)*DD + dd) = o;
                }
            }
        }
    } else {
        #pragma unroll
        for (int mt = 0; mt < 2; mt++) {
            #pragma unroll
            for (int nt = 0; nt < 8; nt++) {
                const int col = bn + warpN*64 + nt*8 + 2*lc;
                const float b0 = bias[col], b1 = bias[col+1];
                #pragma unroll
                for (int rh = 0; rh < 2; rh++) {
                    const int m = bm + warpM*32 + mt*16 + lr + rh*8;
                    float2 o;
                    o.x = acc[mt][nt][rh*2+0] + b0;
                    o.y = acc[mt][nt][rh*2+1] + b1;
                    *(float2*)(out + (size_t)m*CC + col) = o;
                }
            }
        }
    }
}

// ---------------------------------------------------------------------------
// Fused retention (tf32 mma) — R15 version (best measured). k stored natural
// [m][d] pitch 68 (conflict-free stores + reads); vsh [m][e] pitch 72.
// ---------------------------------------------------------------------------
__global__ void __launch_bounds__(256) retention_tf32_kernel(
        const float* __restrict__ mask,
        const float* __restrict__ gamma,
        const float* __restrict__ state_prev) {
    __shared__ uint32_t ksh[64*68];  // [m][d] natural
    __shared__ uint32_t vsh[64*72];  // [m][e] natural; reused: sp [d][e] pitch 72

    const int bh = blockIdx.y;
    const int b = bh & 1, h = bh >> 1;         // mask-L2 pairing
    const int bhq = b*HH + h;
    const int n0 = blockIdx.x * 128;
    const int tid  = threadIdx.x;
    const int lane = tid & 31;
    const int wid  = tid >> 5;
    const int lr = lane >> 2, lc = lane & 3;

    const float* qbase = g_q + (size_t)bhq*NN*DD;
    const float* kbase = g_k + (size_t)bhq*NN*DD;
    const float* vbase = g_v + (size_t)bhq*NN*DD;
    const float* mbase = mask + (size_t)h*NN*NN;

    const int rowg = n0 + wid*16 + lr;

    uint32_t qfr[8][4];
    {
        const float* q0 = qbase + (size_t)rowg*DD;
        const float* q8 = qbase + (size_t)(rowg + 8)*DD;
        #pragma unroll
        for (int ks = 0; ks < 8; ks++) {
            const int col = ks*8 + lc;
            qfr[ks][0] = f2tf(q0[col    ]);
            qfr[ks][1] = f2tf(q8[col    ]);
            qfr[ks][2] = f2tf(q0[col + 4]);
            qfr[ks][3] = f2tf(q8[col + 4]);
        }
    }

    const int idxA = lr*4 + (lc >> 1);
    const int idxB = idxA + 2;
    const bool sel = (lc & 1);

    float o[8][4] = {};

    for (int mt = 0; mt < 32; mt++) {
        const int m0 = mt*64;
        __syncthreads();
        #pragma unroll
        for (int i = 0; i < 4; i++) {
            const int fidx = i*256 + tid;
            const int m = fidx >> 4;
            const int dq = (fidx & 15) * 4;
            const float4 kv = *(const float4*)(kbase + (size_t)(m0 + m)*DD + dq);
            *(uint4*)&ksh[m*68 + dq] =
                make_uint4(f2tf(kv.x), f2tf(kv.y), f2tf(kv.z), f2tf(kv.w));
            const float4 vv = *(const float4*)(vbase + (size_t)(m0 + m)*DD + dq);
            *(uint4*)&vsh[m*72 + dq] =
                make_uint4(f2tf(vv.x), f2tf(vv.y), f2tf(vv.z), f2tf(vv.w));
        }
        __syncthreads();

        float s[8][4] = {};
        #pragma unroll
        for (int ks = 0; ks < 8; ks++) {
            const int col = ks*8 + lc;
            uint32_t bfr[8][2];
            #pragma unroll
            for (int nt = 0; nt < 8; nt++) {
                const int n = nt*8 + lr;
                bfr[nt][0] = ksh[n*68 + col    ];
                bfr[nt][1] = ksh[n*68 + col + 4];
            }
            #pragma unroll
            for (int nt = 0; nt < 8; nt++)
                mma_tf32(s[nt], qfr[ks], bfr[nt], s[nt]);
        }
        #pragma unroll
        for (int nt = 0; nt < 8; nt++) {
            const int colg = m0 + nt*8 + 2*lc;
            const float2 m01 = *(const float2*)(mbase + (size_t)rowg*NN + colg);
            const float2 m23 = *(const float2*)(mbase + (size_t)(rowg+8)*NN + colg);
            s[nt][0] *= m01.x; s[nt][1] *= m01.y;
            s[nt][2] *= m23.x; s[nt][3] *= m23.y;
        }
        #pragma unroll
        for (int ks = 0; ks < 8; ks++) {
            const float t0A = __shfl_sync(0xffffffffu, s[ks][0], idxA);
            const float t1A = __shfl_sync(0xffffffffu, s[ks][1], idxA);
            const float t2A = __shfl_sync(0xffffffffu, s[ks][2], idxA);
            const float t3A = __shfl_sync(0xffffffffu, s[ks][3], idxA);
            const float t0B = __shfl_sync(0xffffffffu, s[ks][0], idxB);
            const float t1B = __shfl_sync(0xffffffffu, s[ks][1], idxB);
            const float t2B = __shfl_sync(0xffffffffu, s[ks][2], idxB);
            const float t3B = __shfl_sync(0xffffffffu, s[ks][3], idxB);
            uint32_t a[4];
            a[0] = f2tf(sel ? t1A : t0A);
            a[1] = f2tf(sel ? t3A : t2A);
            a[2] = f2tf(sel ? t1B : t0B);
            a[3] = f2tf(sel ? t3B : t2B);
            const int col = ks*8 + lc;
            uint32_t bfr[8][2];
            #pragma unroll
            for (int nt = 0; nt < 8; nt++) {
                const int n = nt*8 + lr;
                bfr[nt][0] = vsh[(col    )*72 + n];
                bfr[nt][1] = vsh[(col + 4)*72 + n];
            }
            #pragma unroll
            for (int nt = 0; nt < 8; nt++)
                mma_tf32(o[nt], a, bfr[nt], o[nt]);
        }
    }

    __syncthreads();
    uint32_t* sps = vsh;   // [d][e] pitch 72
    #pragma unroll
    for (int i = 0; i < 4; i++) {
        const int fidx = i*256 + tid;
        const int d = fidx >> 4;
        const int eq = (fidx & 15) * 4;
        const float4 v = *(const float4*)(state_prev + ((size_t)bhq*DD + d)*DD + eq);
        *(uint4*)&sps[d*72 + eq] =
            make_uint4(f2tf(v.x), f2tf(v.y), f2tf(v.z), f2tf(v.w));
    }
    __syncthreads();
    float cr[8][4] = {};
    #pragma unroll
    for (int ks = 0; ks < 8; ks++) {
        const int col = ks*8 + lc;
        uint32_t bfr[8][2];
        #pragma unroll
        for (int nt = 0; nt < 8; nt++) {
            const int n = nt*8 + lr;
            bfr[nt][0] = sps[(col    )*72 + n];
            bfr[nt][1] = sps[(col + 4)*72 + n];
        }
        #pragma unroll
        for (int nt = 0; nt < 8; nt++)
            mma_tf32(cr[nt], qfr[ks], bfr[nt], cr[nt]);
    }
    const float lg = logf(gamma[h]);
    const float sc0 = expf(lg * (float)(rowg + 1));
    const float sc1 = expf(lg * (float)(rowg + 9));
    #pragma unroll
    for (int nt = 0; nt < 8; nt++) {
        o[nt][0] += cr[nt][0]*sc0; o[nt][1] += cr[nt][1]*sc0;
        o[nt][2] += cr[nt][2]*sc1; o[nt][3] += cr[nt][3]*sc1;
    }
    #pragma unroll
    for (int nt = 0; nt < 8; nt++) {
        const int e = nt*8 + 2*lc;
        *(float2*)(g_ret + ((size_t)b*NN + rowg    )*CC + h*64 + e) = make_float2(o[nt][0], o[nt][1]);
        *(float2*)(g_ret + ((size_t)b*NN + rowg + 8)*CC + h*64 + e) = make_float2(o[nt][2], o[nt][3]);
    }
}

// ---------------------------------------------------------------------------
// Kernel 3a: per-chunk partial state (unchanged).
// ---------------------------------------------------------------------------
__global__ void state_partial_kernel(const float* __restrict__ gamma) {
    __shared__ float ksh[64*65];
    __shared__ float vsh[64*65];
    const int chunk = blockIdx.x;
    const int bh    = blockIdx.y;
    const int h = bh & 15;
    const int tid = threadIdx.x;
    const int tx = tid & 15, ty = tid >> 4;
    const int n0 = chunk * 64;
    const float* kbase = g_k + (size_t)bh*NN*DD;
    const float* vbase = g_v + (size_t)bh*NN*DD;
    const float lg = logf(gamma[h]);
    #pragma unroll
    for (int p = 0; p < 16; p++) {
        const int idx = p*256 + tid;
        const int r = idx >> 6, d = idx & 63;
        const int n = n0 + r;
        const float decay = expf(lg * (float)(NN - 1 - n));
        ksh[r*65 + d] = kbase[(size_t)n*DD + d] * decay;
        vsh[r*65 + d] = vbase[(size_t)n*DD + d];
    }
    __syncthreads();
    float acc[4][4] = {};
    #pragma unroll
    for (int r = 0; r < 64; r++) {
        float kk[4], vv[4];
        #pragma unroll
        for (int i = 0; i < 4; i++) kk[i] = ksh[r*65 + ty*4 + i];
        #pragma unroll
        for (int j = 0; j < 4; j++) vv[j] = vsh[r*65 + tx*4 + j];
        #pragma unroll
        for (int i = 0; i < 4; i++)
            #pragma unroll
            for (int j = 0; j < 4; j++)
                acc[i][j] += kk[i]*vv[j];
    }
    float* dst = g_spart + ((size_t)bh*32 + chunk)*DD*DD;
    #pragma unroll
    for (int i = 0; i < 4; i++)
        #pragma unroll
        for (int j = 0; j < 4; j++)
            dst[(ty*4 + i)*DD + tx*4 + j] = acc[i][j];
}

// ---------------------------------------------------------------------------
// Kernel 3b: reduce partials + state_prev*gamma^N -> out_state (unchanged).
// ---------------------------------------------------------------------------
__global__ void state_reduce_kernel(const float* __restrict__ gamma,
                                    const float* __restrict__ state_prev,
                                    float* __restrict__ out_state) {
    const int bh = blockIdx.x;
    const int h = bh & 15;
    const int e = blockIdx.y*256 + threadIdx.x;
    const float cd = expf(logf(gamma[h]) * (float)NN);
    const float* part = g_spart + (size_t)bh*32*DD*DD;
    float sum = 0.0f;
    #pragma unroll
    for (int c = 0; c < 32; c++) sum += part[(size_t)c*DD*DD + e];
    out_state[(size_t)bh*DD*DD + e] = sum + state_prev[(size_t)bh*DD*DD + e]*cd;
}

// ---------------------------------------------------------------------------
extern "C" void kernel_launch(void* const* d_in, const int* in_sizes, int n_in,
                              void* d_out, int out_size) {
    const float* x          = (const float*)d_in[0];
    const float* mask       = (const float*)d_in[1];
    const float* gamma      = (const float*)d_in[2];
    const float* state_prev = (const float*)d_in[3];
    const float* W_qkv      = (const float*)d_in[4];
    const float* b_qkv      = (const float*)d_in[5];
    const float* W_out      = (const float*)d_in[6];
    const float* b_out      = (const float*)d_in[7];
    float* out = (float*)d_out;
    float* out_state = out + (size_t)MM*CC;

    gemm_tf32_kernel<0><<<dim3(C3/128, MM/128), 256>>>(x, W_qkv, b_qkv, nullptr, CC, C3);
    retention_tf32_kernel<<<dim3(NN/128, BB*HH), 256>>>(mask, gamma, state_prev);
    state_partial_kernel<<<dim3(32, BB*HH), 256>>>(gamma);
    state_reduce_kernel<<<dim3(BB*HH, 16), 256>>>(gamma, state_prev, out_state);
    // MODE 1 resolves its A pointer (g_ret) in device code; first arg unused.
    gemm_tf32_kernel<1><<<dim3(CC/128, MM/128), 256>>>(nullptr, W_out, b_out, out, CC, CC);
}